// round 7
// baseline (speedup 1.0000x reference)
#include <cuda_runtime.h>
#include <cstdint>

#define N_ROWS 131072
#define ND 13
#define NS 26
#define NF 39
#define EMB 16
#define DDIM 624           // 39*16
#define HID 32
#define VOCAB 100000
#define EPS 1e-5f

#define ROWS_PER_WARP 4
#define WARPS_B 8
#define ROWS_PER_BLOCK 32  // WARPS_B * ROWS_PER_WARP
#define TPB_B 256

#define NB_STATS 256

// ---------------- device scratch (no allocations allowed) ----------------
__device__ float g_rowsum1[NS * VOCAB];      // 10.4 MB: sum_e T1[f][v][e]
__device__ float g_sw1[ND];
__device__ float g_sb1[ND];
__device__ float g_z1[N_ROWS * HID];         // 16.8 MB: z1 = deep@Wl1 + bl1
__device__ float g_partial[N_ROWS];          // first.sum + fm2.sum + bias
__device__ float g_spart[NB_STATS * 1056];   // per-block partial [S(1024) | sum(32)]
__device__ float g_coef[HID];
__device__ float g_cconst[1];

// ---------------- kernel A1: row sums of T1 ----------------
__global__ void __launch_bounds__(256) k_rowsum(const float* __restrict__ T1) {
    int idx = blockIdx.x * blockDim.x + threadIdx.x;
    if (idx < NS * VOCAB) {
        const float4* p = reinterpret_cast<const float4*>(T1) + (size_t)idx * 4;
        float4 a = p[0], b = p[1], c = p[2], d = p[3];
        g_rowsum1[idx] = ((a.x + a.y) + (a.z + a.w)) + ((b.x + b.y) + (b.z + b.w)) +
                         ((c.x + c.y) + (c.z + c.w)) + ((d.x + d.y) + (d.z + d.w));
    }
}

// ---------------- kernel A2: per-field sums of W1d/b1d ----------------
__global__ void __launch_bounds__(32) k_wsums(const float* __restrict__ W1d,
                                              const float* __restrict__ b1d) {
    int f = threadIdx.x;
    if (f < ND) {
        float sw = 0.f, sb = 0.f;
        for (int e = 0; e < EMB; e++) { sw += W1d[f * EMB + e]; sb += b1d[f * EMB + e]; }
        g_sw1[f] = sw;
        g_sb1[f] = sb;
    }
}

// ---------------- kernel B: main pass ----------------
// per block: 32 rows. Stage second-order embeddings (scaled) into smem,
// compute FM + first-order partial, then z1 = deep @ Wl1 + bl1 (FFMA GEMM).
extern __shared__ float smem[];
__global__ void __launch_bounds__(TPB_B) k_main(
    const float* __restrict__ Xi_dense, const int* __restrict__ Xi_sparse,
    const float* __restrict__ Xv, const float* __restrict__ bias,
    const float* __restrict__ W2d, const float* __restrict__ b2d,
    const float* __restrict__ T2, const float* __restrict__ Wl1,
    const float* __restrict__ bl1)
{
    float* wl1_s = smem;                       // 624*32 = 19968 floats
    float* sec_s = smem + 19968;               // 32 rows * 624 = 19968 floats
    float* xv_s  = smem + 39936;               // 32*39 = 1248
    int*   idx_s = (int*)(smem + 41184);       // 32*26 = 832
    float* xd_s  = smem + 42016;               // 32*13 = 416  (total 42432 floats)

    const int tid = threadIdx.x;
    const int rowbase = blockIdx.x * ROWS_PER_BLOCK;

    for (int j = tid; j < DDIM * HID; j += TPB_B)         wl1_s[j] = Wl1[j];
    for (int j = tid; j < ROWS_PER_BLOCK * NF; j += TPB_B) xv_s[j] = Xv[(size_t)rowbase * NF + j];
    for (int j = tid; j < ROWS_PER_BLOCK * NS; j += TPB_B) idx_s[j] = Xi_sparse[(size_t)rowbase * NS + j];
    for (int j = tid; j < ROWS_PER_BLOCK * ND; j += TPB_B) xd_s[j] = Xi_dense[(size_t)rowbase * ND + j];
    __syncthreads();

    const int warp = tid >> 5;
    const int lane = tid & 31;

    // ---- phase 1: fill sec + FM + first-order, per warp-owned rows ----
    for (int r = 0; r < ROWS_PER_WARP; r++) {
        const int lr  = warp * ROWS_PER_WARP + r;
        const int row = rowbase + lr;
        float* sec_r = sec_s + lr * DDIM;
        float s_acc = 0.f, sq_acc = 0.f;
#pragma unroll
        for (int k = 0; k < 20; k++) {
            int v = k * 32 + lane;
            if (v < DDIM) {
                int f = v >> 4;
                float xv = xv_s[lr * NF + f];
                float val;
                if (v < ND * EMB) {
                    val = fmaf(xd_s[lr * ND + f], W2d[v], b2d[v]);
                } else {
                    int sf = f - ND;
                    long ti = idx_s[lr * NS + sf];
                    val = T2[((long)sf * VOCAB + ti) * EMB + (v & 15)];
                }
                val *= xv;
                sec_r[v] = val;
                s_acc  += val;
                sq_acc  = fmaf(val, val, sq_acc);
            }
        }
        // e = lane&15 is constant per lane; fold lane <-> lane^16 to complete per-e sums
        float s_tot  = s_acc  + __shfl_xor_sync(0xffffffffu, s_acc, 16);
        float sq_tot = sq_acc + __shfl_xor_sync(0xffffffffu, sq_acc, 16);
        float fm = 0.5f * (s_tot * s_tot - sq_tot);   // per-e value, duplicated on 2 lanes

        float fs = 0.f;
        if (lane < NS)
            fs = xv_s[lr * NF + ND + lane] *
                 g_rowsum1[(long)lane * VOCAB + idx_s[lr * NS + lane]];
        if (lane < ND)
            fs += xv_s[lr * NF + lane] * fmaf(xd_s[lr * ND + lane], g_sw1[lane], g_sb1[lane]);

        float x = fs + 0.5f * fm;   // 0.5 corrects the per-e duplication
#pragma unroll
        for (int o = 16; o >= 1; o >>= 1) x += __shfl_xor_sync(0xffffffffu, x, o);
        if (lane == 0) g_partial[row] = x + bias[row];
    }
    __syncwarp();

    // ---- phase 2: z1 = deep @ Wl1 + bl1 (lane = output column, 4 rows/warp) ----
    float acc0 = bl1[lane];
    float acc1 = acc0, acc2 = acc0, acc3 = acc0;
    const float* sec_w = sec_s + warp * ROWS_PER_WARP * DDIM;
#pragma unroll 4
    for (int v4 = 0; v4 < DDIM; v4 += 4) {
        float w0 = wl1_s[(v4 + 0) * HID + lane];
        float w1 = wl1_s[(v4 + 1) * HID + lane];
        float w2 = wl1_s[(v4 + 2) * HID + lane];
        float w3 = wl1_s[(v4 + 3) * HID + lane];
        float4 s0 = *reinterpret_cast<const float4*>(sec_w + 0 * DDIM + v4);
        float4 s1 = *reinterpret_cast<const float4*>(sec_w + 1 * DDIM + v4);
        float4 s2 = *reinterpret_cast<const float4*>(sec_w + 2 * DDIM + v4);
        float4 s3 = *reinterpret_cast<const float4*>(sec_w + 3 * DDIM + v4);
        acc0 = fmaf(s0.x, w0, acc0); acc0 = fmaf(s0.y, w1, acc0); acc0 = fmaf(s0.z, w2, acc0); acc0 = fmaf(s0.w, w3, acc0);
        acc1 = fmaf(s1.x, w0, acc1); acc1 = fmaf(s1.y, w1, acc1); acc1 = fmaf(s1.z, w2, acc1); acc1 = fmaf(s1.w, w3, acc1);
        acc2 = fmaf(s2.x, w0, acc2); acc2 = fmaf(s2.y, w1, acc2); acc2 = fmaf(s2.z, w2, acc2); acc2 = fmaf(s2.w, w3, acc2);
        acc3 = fmaf(s3.x, w0, acc3); acc3 = fmaf(s3.y, w1, acc3); acc3 = fmaf(s3.z, w2, acc3); acc3 = fmaf(s3.w, w3, acc3);
    }
    const int rowg = rowbase + warp * ROWS_PER_WARP;
    g_z1[(rowg + 0) * HID + lane] = acc0;
    g_z1[(rowg + 1) * HID + lane] = acc1;
    g_z1[(rowg + 2) * HID + lane] = acc2;
    g_z1[(rowg + 3) * HID + lane] = acc3;
}

// ---------------- kernel C: partial S = z1^T z1 and sum(z1) ----------------
__global__ void __launch_bounds__(256) k_stats() {
    __shared__ float zt[128 * HID];  // 16 KB tile
    const int tid = threadIdx.x;
    const int i0 = (tid & 7) * 4;    // 4 consecutive i columns
    const int kk = tid >> 3;         // 0..31
    float a0 = 0.f, a1 = 0.f, a2 = 0.f, a3 = 0.f;
    float vx = 0.f, vy = 0.f, vz = 0.f, vw = 0.f;
    const int rows_per_block = N_ROWS / NB_STATS;   // 512
    const int base = blockIdx.x * rows_per_block;
    for (int t = 0; t < rows_per_block / 128; t++) {
        __syncthreads();
        for (int j = tid; j < 128 * HID; j += 256)
            zt[j] = g_z1[(size_t)(base + t * 128) * HID + j];
        __syncthreads();
        for (int r = 0; r < 128; r++) {
            float4 a = *reinterpret_cast<const float4*>(&zt[r * HID + i0]);
            float  b = zt[r * HID + kk];
            a0 = fmaf(a.x, b, a0); a1 = fmaf(a.y, b, a1);
            a2 = fmaf(a.z, b, a2); a3 = fmaf(a.w, b, a3);
            if (kk == 0) { vx += a.x; vy += a.y; vz += a.z; vw += a.w; }
        }
    }
    float* out = g_spart + blockIdx.x * 1056;
    out[kk * HID + i0 + 0] = a0;
    out[kk * HID + i0 + 1] = a1;
    out[kk * HID + i0 + 2] = a2;
    out[kk * HID + i0 + 3] = a3;
    if (kk == 0) {
        out[1024 + i0 + 0] = vx; out[1024 + i0 + 1] = vy;
        out[1024 + i0 + 2] = vz; out[1024 + i0 + 3] = vw;
    }
}

// ---------------- kernel D: closed-form BN folding ----------------
// 256 threads (1024 caused reg-file overflow -> "too many resources").
__global__ void __launch_bounds__(256) k_finalize(
    const float* __restrict__ Wl2, const float* __restrict__ bl2,
    const float* __restrict__ g1, const float* __restrict__ be1,
    const float* __restrict__ g2, const float* __restrict__ be2) {
    __shared__ float Ssm[1024];
    __shared__ float sum_s[32];
    __shared__ float a1_s[32], c1_s[32], m1_s[32], w2_s[32], d_s[32], m2_s[32];
    const int tid = threadIdx.x;  // 256 threads
    // Reduce per-block partials: each thread owns 4 entries of S.
#pragma unroll
    for (int q4 = 0; q4 < 4; q4++) {
        const int e = q4 * 256 + tid;
        float acc = 0.f;
        for (int b = 0; b < NB_STATS; b++) acc += g_spart[b * 1056 + e];
        Ssm[e] = acc;
    }
    if (tid < 32) {
        float s = 0.f;
        for (int b = 0; b < NB_STATS; b++) s += g_spart[b * 1056 + 1024 + tid];
        sum_s[tid] = s;
    }
    __syncthreads();
    if (tid < 32) {
        const float invN = 1.0f / (float)N_ROWS;
        // BN1 params (i = tid)
        float m1 = sum_s[tid] * invN;
        float v1 = Ssm[tid * HID + tid] * invN - m1 * m1;
        float a1 = g1[tid] * rsqrtf(v1 + EPS);
        a1_s[tid] = a1; m1_s[tid] = m1; c1_s[tid] = be1[tid] - a1 * m1;
        __syncwarp();
        // layer 2, j = tid:  z2_j = sum_i a1_i z1_i Wl2[i][j] + d_j
        float d = bl2[tid], mA = 0.f;
        for (int i = 0; i < 32; i++) {
            float wij = Wl2[i * HID + tid];
            d  += c1_s[i] * wij;
            mA += a1_s[i] * wij * m1_s[i];
        }
        float m2 = mA + d;
        // E[z2^2] via S
        float q = 0.f;
        for (int i = 0; i < 32; i++) {
            float Ai = a1_s[i] * Wl2[i * HID + tid];
            float inner = 0.f;
            for (int k = 0; k < 32; k++)
                inner += Ssm[i * HID + k] * a1_s[k] * Wl2[k * HID + tid];
            q += Ai * inner;
        }
        float Ez2 = q * invN + 2.f * d * mA + d * d;
        float v2 = Ez2 - m2 * m2;
        float w2 = g2[tid] * rsqrtf(v2 + EPS);
        w2_s[tid] = w2; d_s[tid] = d; m2_s[tid] = m2;
        __syncwarp();
        // per-row h.sum = coef . z1 + const
        float cf = 0.f;
        for (int j = 0; j < 32; j++) cf += Wl2[tid * HID + j] * w2_s[j];
        g_coef[tid] = a1_s[tid] * cf;
        float cpart = w2_s[tid] * d_s[tid] - w2_s[tid] * m2_s[tid] + be2[tid];
        for (int o = 16; o >= 1; o >>= 1) cpart += __shfl_xor_sync(0xffffffffu, cpart, o);
        if (tid == 0) g_cconst[0] = cpart;
    }
}

// ---------------- kernel E: final output ----------------
__global__ void __launch_bounds__(256) k_output(float* __restrict__ out) {
    __shared__ float zt[256 * 33];  // padded to kill bank conflicts
    __shared__ float cf[32];
    const int tid = threadIdx.x;
    const int base = blockIdx.x * 256;
    if (tid < 32) cf[tid] = g_coef[tid];
    for (int j = tid; j < 256 * HID; j += 256)
        zt[(j >> 5) * 33 + (j & 31)] = g_z1[(size_t)base * HID + j];
    __syncthreads();
    float acc = g_partial[base + tid] + g_cconst[0];
    const float* zr = zt + tid * 33;
#pragma unroll
    for (int i = 0; i < 32; i++) acc = fmaf(cf[i], zr[i], acc);
    out[base + tid] = acc;
}

// ---------------- launch ----------------
extern "C" void kernel_launch(void* const* d_in, const int* in_sizes, int n_in,
                              void* d_out, int out_size) {
    const float* Xi_dense = (const float*)d_in[0];
    const int*   Xi_sparse= (const int*)  d_in[1];
    const float* Xv       = (const float*)d_in[2];
    const float* bias     = (const float*)d_in[3];
    const float* W1d      = (const float*)d_in[4];
    const float* b1d      = (const float*)d_in[5];
    const float* T1       = (const float*)d_in[6];
    const float* W2d      = (const float*)d_in[7];
    const float* b2d      = (const float*)d_in[8];
    const float* T2       = (const float*)d_in[9];
    const float* Wl1      = (const float*)d_in[10];
    const float* bl1      = (const float*)d_in[11];
    const float* g1       = (const float*)d_in[12];
    const float* be1      = (const float*)d_in[13];
    const float* Wl2      = (const float*)d_in[14];
    const float* bl2      = (const float*)d_in[15];
    const float* g2       = (const float*)d_in[16];
    const float* be2      = (const float*)d_in[17];
    float* out = (float*)d_out;

    const int smem_b = 42432 * (int)sizeof(float);  // 169,728 B
    // Unconditional every call: no static guards (harness rule), capture-safe.
    cudaFuncSetAttribute(k_main, cudaFuncAttributeMaxDynamicSharedMemorySize, smem_b);

    k_rowsum<<<(NS * VOCAB + 255) / 256, 256>>>(T1);
    k_wsums<<<1, 32>>>(W1d, b1d);
    k_main<<<N_ROWS / ROWS_PER_BLOCK, TPB_B, smem_b>>>(
        Xi_dense, Xi_sparse, Xv, bias, W2d, b2d, T2, Wl1, bl1);
    k_stats<<<NB_STATS, 256>>>();
    k_finalize<<<1, 256>>>(Wl2, bl2, g1, be1, g2, be2);
    k_output<<<N_ROWS / 256, 256>>>(out);
}

// round 8
// speedup vs baseline: 1.4695x; 1.4695x over previous
#include <cuda_runtime.h>
#include <cstdint>

#define N_ROWS 131072
#define ND 13
#define NS 26
#define NF 39
#define EMB 16
#define DDIM 624           // 39*16
#define HID 32
#define VOCAB 100000
#define EPS 1e-5f

#define ROWS_PER_WARP 4
#define WARPS_B 8
#define ROWS_PER_BLOCK 32
#define TPB_B 256

// K-chunking: chunk 0 = v [0,320) (fields 0..19), chunk 1 = v [320,624) (fields 20..38)
#define CHUNK0 320
#define CHUNK1 304
#define SEC_STRIDE 324     // 324 % 32 == 4 -> bank = 4*g + t + c, conflict-free A-frag loads
#define WL1_STRIDE 36      // 36 % 32 == 4  -> bank = 4*k + col, conflict-free B-frag loads

#define NB_STATS 256

// ---------------- device scratch ----------------
__device__ float g_rowsum1[NS * VOCAB];      // 10.4 MB: sum_e T1[f][v][e]
__device__ float g_sw1[ND];
__device__ float g_sb1[ND];
__device__ float g_z1[N_ROWS * HID];         // z1 = deep@Wl1 + bl1
__device__ float g_partial[N_ROWS];          // first.sum + fm2.sum + bias
__device__ float g_spart[NB_STATS * 1056];   // per-block partial [S(1024) | sum(32)]
__device__ float g_coef[HID];
__device__ float g_cconst[1];

// ---------------- tf32 helpers ----------------
__device__ __forceinline__ uint32_t f2tf32(float x) {
    uint32_t u;
    asm("cvt.rna.tf32.f32 %0, %1;" : "=r"(u) : "f"(x));
    return u;
}

__device__ __forceinline__ void mma_tf32(float& d0, float& d1, float& d2, float& d3,
                                         uint32_t a0, uint32_t a1, uint32_t a2, uint32_t a3,
                                         uint32_t b0, uint32_t b1) {
    asm volatile(
        "mma.sync.aligned.m16n8k8.row.col.f32.tf32.tf32.f32 "
        "{%0,%1,%2,%3},{%4,%5,%6,%7},{%8,%9},{%0,%1,%2,%3};"
        : "+f"(d0), "+f"(d1), "+f"(d2), "+f"(d3)
        : "r"(a0), "r"(a1), "r"(a2), "r"(a3), "r"(b0), "r"(b1));
}

// ---------------- kernel A1: row sums of T1 ----------------
__global__ void __launch_bounds__(256) k_rowsum(const float* __restrict__ T1) {
    int idx = blockIdx.x * blockDim.x + threadIdx.x;
    if (idx < NS * VOCAB) {
        const float4* p = reinterpret_cast<const float4*>(T1) + (size_t)idx * 4;
        float4 a = p[0], b = p[1], c = p[2], d = p[3];
        g_rowsum1[idx] = ((a.x + a.y) + (a.z + a.w)) + ((b.x + b.y) + (b.z + b.w)) +
                         ((c.x + c.y) + (c.z + c.w)) + ((d.x + d.y) + (d.z + d.w));
    }
}

// ---------------- kernel A2: per-field sums of W1d/b1d ----------------
__global__ void __launch_bounds__(32) k_wsums(const float* __restrict__ W1d,
                                              const float* __restrict__ b1d) {
    int f = threadIdx.x;
    if (f < ND) {
        float sw = 0.f, sb = 0.f;
        for (int e = 0; e < EMB; e++) { sw += W1d[f * EMB + e]; sb += b1d[f * EMB + e]; }
        g_sw1[f] = sw;
        g_sb1[f] = sb;
    }
}

// ---------------- kernel B: main fused pass (K-chunked, tf32-split MMA) ----------------
extern __shared__ float smem[];
__global__ void __launch_bounds__(TPB_B) k_main(
    const float* __restrict__ Xi_dense, const int* __restrict__ Xi_sparse,
    const float* __restrict__ Xv, const float* __restrict__ bias,
    const float* __restrict__ W2d, const float* __restrict__ b2d,
    const float* __restrict__ T2, const float* __restrict__ Wl1,
    const float* __restrict__ bl1)
{
    // smem layout (floats):
    //   sec_s : 32 * 324            = 10368
    //   wl1_s : 320 * 36            = 11520
    //   xv_s  : 32*39 = 1248, idx_s : 832, xd_s : 416
    float* sec_s = smem;                         // 10368
    float* wl1_s = smem + 10368;                 // 11520
    float* xv_s  = smem + 21888;                 // 1248
    int*   idx_s = (int*)(smem + 23136);         // 832
    float* xd_s  = smem + 23968;                 // 416   (total 24384 floats = 97536 B)

    const int tid = threadIdx.x;
    const int rowbase = blockIdx.x * ROWS_PER_BLOCK;

    for (int j = tid; j < ROWS_PER_BLOCK * NF; j += TPB_B) xv_s[j] = Xv[(size_t)rowbase * NF + j];
    for (int j = tid; j < ROWS_PER_BLOCK * NS; j += TPB_B) idx_s[j] = Xi_sparse[(size_t)rowbase * NS + j];
    for (int j = tid; j < ROWS_PER_BLOCK * ND; j += TPB_B) xd_s[j] = Xi_dense[(size_t)rowbase * ND + j];

    const int warp = tid >> 5;
    const int lane = tid & 31;

    // mma tile mapping: warp -> (m-tile, n-tile); lane -> (group g, thread t)
    const int mt = warp >> 2;          // 0..1
    const int nt = warp & 3;           // 0..3
    const int g  = lane >> 2;          // 0..7
    const int t  = lane & 3;           // 0..3

    float d0 = 0.f, d1 = 0.f, d2 = 0.f, d3 = 0.f;   // z1 accumulators (persist over chunks)
    float s_acc[ROWS_PER_WARP]  = {0.f, 0.f, 0.f, 0.f};
    float sq_acc[ROWS_PER_WARP] = {0.f, 0.f, 0.f, 0.f};

#pragma unroll
    for (int chunk = 0; chunk < 2; chunk++) {
        const int c0 = chunk ? CHUNK0 : 0;
        const int CL = chunk ? CHUNK1 : CHUNK0;

        // ---- load Wl1 chunk into smem [k][col], stride 36 ----
        for (int j = tid; j < CL * HID; j += TPB_B) {
            int kk = j >> 5, c = j & 31;
            wl1_s[kk * WL1_STRIDE + c] = Wl1[(size_t)(c0 + kk) * HID + c];
        }
        if (chunk == 0) __syncthreads();   // xv/idx/xd ready before phase 1

        // ---- phase 1: fill sec chunk + FM partials ----
        for (int r = 0; r < ROWS_PER_WARP; r++) {
            const int lr = warp * ROWS_PER_WARP + r;
            float* sec_r = sec_s + lr * SEC_STRIDE;
            float sa = s_acc[r], sqa = sq_acc[r];
#pragma unroll
            for (int k = 0; k < 10; k++) {
                int vloc = k * 32 + lane;
                int v = c0 + vloc;
                if (vloc < CL) {
                    int f = v >> 4;
                    float xv = xv_s[lr * NF + f];
                    float val;
                    if (v < ND * EMB) {
                        val = fmaf(xd_s[lr * ND + f], W2d[v], b2d[v]);
                    } else {
                        int sf = f - ND;
                        long ti = idx_s[lr * NS + sf];
                        val = T2[((long)sf * VOCAB + ti) * EMB + (v & 15)];
                    }
                    val *= xv;
                    sec_r[vloc] = val;
                    sa  += val;
                    sqa  = fmaf(val, val, sqa);
                }
            }
            s_acc[r] = sa; sq_acc[r] = sqa;
        }
        __syncthreads();

        // ---- phase 2: split-tf32 MMA  z1-tile += sec_chunk @ Wl1_chunk ----
        const float* A0 = sec_s + (mt * 16 + g) * SEC_STRIDE;
        const float* A1 = A0 + 8 * SEC_STRIDE;
        const int bcol = nt * 8 + g;
        for (int k0 = 0; k0 < CL; k0 += 8) {
            float a0f = A0[k0 + t],     a1f = A1[k0 + t];
            float a2f = A0[k0 + t + 4], a3f = A1[k0 + t + 4];
            float b0f = wl1_s[(k0 + t) * WL1_STRIDE + bcol];
            float b1f = wl1_s[(k0 + t + 4) * WL1_STRIDE + bcol];
            uint32_t a0h = f2tf32(a0f), a1h = f2tf32(a1f), a2h = f2tf32(a2f), a3h = f2tf32(a3f);
            uint32_t b0h = f2tf32(b0f), b1h = f2tf32(b1f);
            uint32_t a0l = f2tf32(a0f - __uint_as_float(a0h));
            uint32_t a1l = f2tf32(a1f - __uint_as_float(a1h));
            uint32_t a2l = f2tf32(a2f - __uint_as_float(a2h));
            uint32_t a3l = f2tf32(a3f - __uint_as_float(a3h));
            uint32_t b0l = f2tf32(b0f - __uint_as_float(b0h));
            uint32_t b1l = f2tf32(b1f - __uint_as_float(b1h));
            mma_tf32(d0, d1, d2, d3, a0h, a1h, a2h, a3h, b0h, b1h);
            mma_tf32(d0, d1, d2, d3, a0h, a1h, a2h, a3h, b0l, b1l);
            mma_tf32(d0, d1, d2, d3, a0l, a1l, a2l, a3l, b0h, b1h);
        }
        __syncthreads();   // before chunk 1 overwrites sec_s / wl1_s
    }

    // ---- FM + first-order finalize (per warp-owned rows) ----
    for (int r = 0; r < ROWS_PER_WARP; r++) {
        const int lr  = warp * ROWS_PER_WARP + r;
        const int row = rowbase + lr;
        // per-e partials live on lane & lane^16 (e = lane & 15)
        float s_tot  = s_acc[r]  + __shfl_xor_sync(0xffffffffu, s_acc[r], 16);
        float sq_tot = sq_acc[r] + __shfl_xor_sync(0xffffffffu, sq_acc[r], 16);
        float fm = 0.5f * (s_tot * s_tot - sq_tot);   // per-e, duplicated on 2 lanes

        float fs = 0.f;
        if (lane < NS)
            fs = xv_s[lr * NF + ND + lane] *
                 g_rowsum1[(long)lane * VOCAB + idx_s[lr * NS + lane]];
        if (lane < ND)
            fs += xv_s[lr * NF + lane] * fmaf(xd_s[lr * ND + lane], g_sw1[lane], g_sb1[lane]);

        float x = fs + 0.5f * fm;   // 0.5 corrects per-e duplication
#pragma unroll
        for (int o = 16; o >= 1; o >>= 1) x += __shfl_xor_sync(0xffffffffu, x, o);
        if (lane == 0) g_partial[row] = x + bias[row];
    }

    // ---- write z1 tile: D rows mt*16+{g,g+8}, cols nt*8+{2t,2t+1} ----
    {
        const int col0 = nt * 8 + 2 * t;
        const int r0 = rowbase + mt * 16 + g;
        const int r1 = r0 + 8;
        const float bA = bl1[col0], bB = bl1[col0 + 1];
        g_z1[(size_t)r0 * HID + col0]     = d0 + bA;
        g_z1[(size_t)r0 * HID + col0 + 1] = d1 + bB;
        g_z1[(size_t)r1 * HID + col0]     = d2 + bA;
        g_z1[(size_t)r1 * HID + col0 + 1] = d3 + bB;
    }
}

// ---------------- kernel C: partial S = z1^T z1 and sum(z1) ----------------
__global__ void __launch_bounds__(256) k_stats() {
    __shared__ float zt[128 * HID];  // 16 KB tile
    const int tid = threadIdx.x;
    const int i0 = (tid & 7) * 4;
    const int kk = tid >> 3;
    float a0 = 0.f, a1 = 0.f, a2 = 0.f, a3 = 0.f;
    float vx = 0.f, vy = 0.f, vz = 0.f, vw = 0.f;
    const int rows_per_block = N_ROWS / NB_STATS;   // 512
    const int base = blockIdx.x * rows_per_block;
    for (int tI = 0; tI < rows_per_block / 128; tI++) {
        __syncthreads();
        for (int j = tid; j < 128 * HID; j += 256)
            zt[j] = g_z1[(size_t)(base + tI * 128) * HID + j];
        __syncthreads();
        for (int r = 0; r < 128; r++) {
            float4 a = *reinterpret_cast<const float4*>(&zt[r * HID + i0]);
            float  b = zt[r * HID + kk];
            a0 = fmaf(a.x, b, a0); a1 = fmaf(a.y, b, a1);
            a2 = fmaf(a.z, b, a2); a3 = fmaf(a.w, b, a3);
            if (kk == 0) { vx += a.x; vy += a.y; vz += a.z; vw += a.w; }
        }
    }
    float* out = g_spart + blockIdx.x * 1056;
    out[kk * HID + i0 + 0] = a0;
    out[kk * HID + i0 + 1] = a1;
    out[kk * HID + i0 + 2] = a2;
    out[kk * HID + i0 + 3] = a3;
    if (kk == 0) {
        out[1024 + i0 + 0] = vx; out[1024 + i0 + 1] = vy;
        out[1024 + i0 + 2] = vz; out[1024 + i0 + 3] = vw;
    }
}

// ---------------- kernel D: closed-form BN folding ----------------
__global__ void __launch_bounds__(256) k_finalize(
    const float* __restrict__ Wl2, const float* __restrict__ bl2,
    const float* __restrict__ g1, const float* __restrict__ be1,
    const float* __restrict__ g2, const float* __restrict__ be2) {
    __shared__ float Ssm[1024];
    __shared__ float sum_s[32];
    __shared__ float a1_s[32], c1_s[32], m1_s[32], w2_s[32], d_s[32], m2_s[32];
    const int tid = threadIdx.x;  // 256 threads
#pragma unroll
    for (int q4 = 0; q4 < 4; q4++) {
        const int e = q4 * 256 + tid;
        float acc = 0.f;
        for (int b = 0; b < NB_STATS; b++) acc += g_spart[b * 1056 + e];
        Ssm[e] = acc;
    }
    if (tid < 32) {
        float s = 0.f;
        for (int b = 0; b < NB_STATS; b++) s += g_spart[b * 1056 + 1024 + tid];
        sum_s[tid] = s;
    }
    __syncthreads();
    if (tid < 32) {
        const float invN = 1.0f / (float)N_ROWS;
        float m1 = sum_s[tid] * invN;
        float v1 = Ssm[tid * HID + tid] * invN - m1 * m1;
        float a1 = g1[tid] * rsqrtf(v1 + EPS);
        a1_s[tid] = a1; m1_s[tid] = m1; c1_s[tid] = be1[tid] - a1 * m1;
        __syncwarp();
        float d = bl2[tid], mA = 0.f;
        for (int i = 0; i < 32; i++) {
            float wij = Wl2[i * HID + tid];
            d  += c1_s[i] * wij;
            mA += a1_s[i] * wij * m1_s[i];
        }
        float m2 = mA + d;
        float q = 0.f;
        for (int i = 0; i < 32; i++) {
            float Ai = a1_s[i] * Wl2[i * HID + tid];
            float inner = 0.f;
            for (int k = 0; k < 32; k++)
                inner += Ssm[i * HID + k] * a1_s[k] * Wl2[k * HID + tid];
            q += Ai * inner;
        }
        float Ez2 = q * invN + 2.f * d * mA + d * d;
        float v2 = Ez2 - m2 * m2;
        float w2 = g2[tid] * rsqrtf(v2 + EPS);
        w2_s[tid] = w2; d_s[tid] = d; m2_s[tid] = m2;
        __syncwarp();
        float cf = 0.f;
        for (int j = 0; j < 32; j++) cf += Wl2[tid * HID + j] * w2_s[j];
        g_coef[tid] = a1_s[tid] * cf;
        float cpart = w2_s[tid] * d_s[tid] - w2_s[tid] * m2_s[tid] + be2[tid];
        for (int o = 16; o >= 1; o >>= 1) cpart += __shfl_xor_sync(0xffffffffu, cpart, o);
        if (tid == 0) g_cconst[0] = cpart;
    }
}

// ---------------- kernel E: final output ----------------
__global__ void __launch_bounds__(256) k_output(float* __restrict__ out) {
    __shared__ float zt[256 * 33];
    __shared__ float cf[32];
    const int tid = threadIdx.x;
    const int base = blockIdx.x * 256;
    if (tid < 32) cf[tid] = g_coef[tid];
    for (int j = tid; j < 256 * HID; j += 256)
        zt[(j >> 5) * 33 + (j & 31)] = g_z1[(size_t)base * HID + j];
    __syncthreads();
    float acc = g_partial[base + tid] + g_cconst[0];
    const float* zr = zt + tid * 33;
#pragma unroll
    for (int i = 0; i < 32; i++) acc = fmaf(cf[i], zr[i], acc);
    out[base + tid] = acc;
}

// ---------------- launch ----------------
extern "C" void kernel_launch(void* const* d_in, const int* in_sizes, int n_in,
                              void* d_out, int out_size) {
    const float* Xi_dense = (const float*)d_in[0];
    const int*   Xi_sparse= (const int*)  d_in[1];
    const float* Xv       = (const float*)d_in[2];
    const float* bias     = (const float*)d_in[3];
    const float* W1d      = (const float*)d_in[4];
    const float* b1d      = (const float*)d_in[5];
    const float* T1       = (const float*)d_in[6];
    const float* W2d      = (const float*)d_in[7];
    const float* b2d      = (const float*)d_in[8];
    const float* T2       = (const float*)d_in[9];
    const float* Wl1      = (const float*)d_in[10];
    const float* bl1      = (const float*)d_in[11];
    const float* g1       = (const float*)d_in[12];
    const float* be1      = (const float*)d_in[13];
    const float* Wl2      = (const float*)d_in[14];
    const float* bl2      = (const float*)d_in[15];
    const float* g2       = (const float*)d_in[16];
    const float* be2      = (const float*)d_in[17];
    float* out = (float*)d_out;

    const int smem_b = 24384 * (int)sizeof(float);  // 97,536 B -> 2 blocks/SM
    cudaFuncSetAttribute(k_main, cudaFuncAttributeMaxDynamicSharedMemorySize, smem_b);

    k_rowsum<<<(NS * VOCAB + 255) / 256, 256>>>(T1);
    k_wsums<<<1, 32>>>(W1d, b1d);
    k_main<<<N_ROWS / ROWS_PER_BLOCK, TPB_B, smem_b>>>(
        Xi_dense, Xi_sparse, Xv, bias, W2d, b2d, T2, Wl1, bl1);
    k_stats<<<NB_STATS, 256>>>();
    k_finalize<<<1, 256>>>(Wl2, bl2, g1, be1, g2, be2);
    k_output<<<N_ROWS / 256, 256>>>(out);
}